// round 2
// baseline (speedup 1.0000x reference)
#include <cuda_runtime.h>
#include <math.h>

// Problem constants (fixed-shape problem)
#define NA_N   40000
#define NB_N   40000
#define EPS_LN 1e-5f

#define WARPS_PER_BLK 16
#define EDGE_BLOCKS   148          // per edge type
#define EDGE_STRIDE   (EDGE_BLOCKS * WARPS_PER_BLK)

// Scratch: per-type accumulators and counts (static device arrays; no runtime alloc)
__device__ float g_acc[2ull * NA_N * 256ull];
__device__ int   g_cnt[2 * NA_N];

// ---------------------------------------------------------------------------
// helpers
// ---------------------------------------------------------------------------
__device__ __forceinline__ float warp_sum(float v) {
#pragma unroll
    for (int o = 16; o; o >>= 1) v += __shfl_xor_sync(0xffffffffu, v, o);
    return v;
}
__device__ __forceinline__ float warp_max(float v) {
#pragma unroll
    for (int o = 16; o; o >>= 1) v = fmaxf(v, __shfl_xor_sync(0xffffffffu, v, o));
    return v;
}

// out[s][f] partials over 64-dim reduction. Weights transposed [c][f] in smem
// (conflict-free: lane -> consecutive f). Input rows read as broadcast float4 LDS.
// Lane owns features (lane, lane+32).
template <int S>
__device__ __forceinline__ void mm64_core(const float* __restrict__ in, int in_stride,
                                          const float* __restrict__ Wt, int wstride,
                                          int lane, float* a0, float* a1) {
#pragma unroll
    for (int s = 0; s < S; s++) { a0[s] = 0.f; a1[s] = 0.f; }
#pragma unroll
    for (int c4 = 0; c4 < 16; c4++) {
        float4 xv[S];
#pragma unroll
        for (int s = 0; s < S; s++)
            xv[s] = *reinterpret_cast<const float4*>(in + s * in_stride + (c4 << 2));
#pragma unroll
        for (int j = 0; j < 4; j++) {
            const float* wrow = Wt + ((c4 << 2) + j) * wstride;
            float w0 = wrow[lane];
            float w1 = wrow[lane + 32];
#pragma unroll
            for (int s = 0; s < S; s++) {
                float xx = (j == 0) ? xv[s].x : (j == 1) ? xv[s].y : (j == 2) ? xv[s].z : xv[s].w;
                a0[s] = fmaf(xx, w0, a0[s]);
                a1[s] = fmaf(xx, w1, a1[s]);
            }
        }
    }
}

template <int S, bool RELU>
__device__ __forceinline__ void mm64_store(const float* __restrict__ in, int in_stride,
                                           const float* __restrict__ Wt, int wstride,
                                           float b0, float b1,
                                           float* __restrict__ out, int out_stride, int lane) {
    float a0[S], a1[S];
    mm64_core<S>(in, in_stride, Wt, wstride, lane, a0, a1);
#pragma unroll
    for (int s = 0; s < S; s++) {
        float r0 = a0[s] + b0, r1 = a1[s] + b1;
        if (RELU) { r0 = fmaxf(r0, 0.f); r1 = fmaxf(r1, 0.f); }
        out[s * out_stride + lane]      = r0;
        out[s * out_stride + lane + 32] = r1;
    }
}

// LayerNorm over 64 features distributed as (lane, lane+32).
__device__ __forceinline__ void ln_pair(float r0, float r1,
                                        float gg0, float gg1, float bb0, float bb1,
                                        float& y0, float& y1) {
    float m = warp_sum(r0 + r1) * (1.f / 64.f);
    float d0 = r0 - m, d1 = r1 - m;
    float v = warp_sum(d0 * d0 + d1 * d1) * (1.f / 64.f);
    float inv = rsqrtf(v + EPS_LN);
    y0 = d0 * inv * gg0 + bb0;
    y1 = d1 * inv * gg1 + bb1;
}

// ---------------------------------------------------------------------------
// zero scratch
// ---------------------------------------------------------------------------
__global__ void zero_kernel() {
    size_t i = (size_t)blockIdx.x * blockDim.x + threadIdx.x;
    size_t stride = (size_t)gridDim.x * blockDim.x;
    float4* p = reinterpret_cast<float4*>(g_acc);
    size_t n4 = (2ull * NA_N * 256ull) / 4;
    for (size_t j = i; j < n4; j += stride) p[j] = make_float4(0.f, 0.f, 0.f, 0.f);
    for (size_t j = i; j < 2 * NA_N; j += stride) g_cnt[j] = 0;
}

// ---------------------------------------------------------------------------
// per-edge transformer. grid = 2*EDGE_BLOCKS: type = blockIdx&1.
// One warp = one edge; only tokens 0..3 materialized after attention.
// Per-warp smem (1792 floats): xi[256] | xjff[256] | qox[256] | k[512] | v[512]
//   xs staged into k-region (dead before k is written)
//   q -> attn-out -> LN1-out all alias in qox
//   FF1 output aliases xj (dead after k/v mm64s)
// ---------------------------------------------------------------------------
__global__ void __launch_bounds__(512, 1) edge_kernel(
    const float* __restrict__ xA, const float* __restrict__ xB,
    const int* __restrict__ e0, int E0,
    const int* __restrict__ e1, int E1,
    const float* __restrict__ Wb,  const float* __restrict__ bb,
    const float* __restrict__ Wqkv,const float* __restrict__ bqkv,
    const float* __restrict__ Wo,  const float* __restrict__ bo,
    const float* __restrict__ g1,  const float* __restrict__ be1,
    const float* __restrict__ W1,  const float* __restrict__ bf1,
    const float* __restrict__ W2,  const float* __restrict__ bf2,
    const float* __restrict__ g2,  const float* __restrict__ be2) {
    extern __shared__ float smem[];
    float* sWb  = smem;              // [c][f]     64*64
    float* sWq  = sWb + 4096;        // [c][g]     64*192
    float* sWo  = sWq + 12288;       // [c][f]     64*64
    float* sW1  = sWo + 4096;        // [c][f]     64*64
    float* sW2  = sW1 + 4096;        // [f][c]     64*64
    float* bufs = sW2 + 4096;        // 16 warps * 1792 floats

    const int type = blockIdx.x & 1;
    const int bidx = blockIdx.x >> 1;
    const int tid = threadIdx.x;

    // Stage weights (transposed so the reduction dim is the smem row)
    {
        const float* p;
        p = Wb + type * 4096;
        for (int i = tid; i < 4096; i += 512)  { int f = i >> 6, c = i & 63; sWb[c * 64 + f] = p[i]; }
        p = Wqkv + type * 12288;
        for (int i = tid; i < 12288; i += 512) { int g = i >> 6, c = i & 63; sWq[c * 192 + g] = p[i]; }
        p = Wo + type * 4096;
        for (int i = tid; i < 4096; i += 512)  { int f = i >> 6, c = i & 63; sWo[c * 64 + f] = p[i]; }
        p = W1 + type * 4096;
        for (int i = tid; i < 4096; i += 512)  { int f = i >> 6, c = i & 63; sW1[c * 64 + f] = p[i]; }
        p = W2 + type * 4096;                  // (C, FF): out c = sum_f  ->  sW2[f][c]
        for (int i = tid; i < 4096; i += 512)  { int c = i >> 6, f = i & 63; sW2[f * 64 + c] = p[i]; }
    }
    __syncthreads();

    const int warp = tid >> 5, lane = tid & 31;
    float* xi   = bufs + warp * 1792;
    float* xjff = xi + 256;
    float* qox  = xjff + 256;
    float* kbuf = qox + 256;     // xs staged here first
    float* vbuf = kbuf + 512;

    const float* xsrc = type ? xA : xB;
    const int*   ei   = type ? e1 : e0;
    const int    E    = type ? E1 : E0;
    float* accbase = g_acc + (size_t)type * NA_N * 256ull;
    int*   cntbase = g_cnt + type * NA_N;

    // Hoist all per-lane constants (biases / LN params) into registers
    const float cbb0  = __ldg(bb   + type * 64 + lane),  cbb1  = __ldg(bb   + type * 64 + lane + 32);
    const float cbq0  = __ldg(bqkv + type * 192 + lane),        cbq0b = __ldg(bqkv + type * 192 + lane + 32);
    const float cbk0  = __ldg(bqkv + type * 192 + 64 + lane),   cbk1  = __ldg(bqkv + type * 192 + 64 + lane + 32);
    const float cbv0  = __ldg(bqkv + type * 192 + 128 + lane),  cbv1  = __ldg(bqkv + type * 192 + 128 + lane + 32);
    const float cbo0  = __ldg(bo   + type * 64 + lane),  cbo1  = __ldg(bo   + type * 64 + lane + 32);
    const float cbf10 = __ldg(bf1  + type * 64 + lane),  cbf11 = __ldg(bf1  + type * 64 + lane + 32);
    const float cbf20 = __ldg(bf2  + type * 64 + lane),  cbf21 = __ldg(bf2  + type * 64 + lane + 32);
    const float cg10  = __ldg(g1   + type * 64 + lane),  cg11  = __ldg(g1   + type * 64 + lane + 32);
    const float cbe10 = __ldg(be1  + type * 64 + lane),  cbe11 = __ldg(be1  + type * 64 + lane + 32);
    const float cg20  = __ldg(g2   + type * 64 + lane),  cg21  = __ldg(g2   + type * 64 + lane + 32);
    const float cbe20 = __ldg(be2  + type * 64 + lane),  cbe21 = __ldg(be2  + type * 64 + lane + 32);

    for (int e = bidx * WARPS_PER_BLK + warp; e < E; e += EDGE_STRIDE) {
        const int src = __ldg(ei + e);
        const int dst = __ldg(ei + E + e);

        // Stage xi, xs (coalesced LDG.128 -> smem; all later reads are LDS broadcast)
        {
            const float4* gxi = reinterpret_cast<const float4*>(xA + (size_t)dst * 256);
            const float4* gxs = reinterpret_cast<const float4*>(xsrc + (size_t)src * 256);
            float4* sxi = reinterpret_cast<float4*>(xi);
            float4* sxs = reinterpret_cast<float4*>(kbuf);
            sxi[lane]      = __ldg(gxi + lane);
            sxi[lane + 32] = __ldg(gxi + lane + 32);
            sxs[lane]      = __ldg(gxs + lane);
            sxs[lane + 32] = __ldg(gxs + lane + 32);
        }
        __syncwarp();

        // b_proj: xs(kbuf) -> xj
        mm64_store<4, false>(kbuf, 64, sWb, 64, cbb0, cbb1, xjff, 64, lane);
        __syncwarp();

        // q (rows 0..3 only), k, v
        mm64_store<4, false>(xi,   64, sWq + 0,   192, cbq0, cbq0b, qox,        64, lane);
        mm64_store<4, false>(xi,   64, sWq + 64,  192, cbk0, cbk1,  kbuf,       64, lane);
        mm64_store<4, false>(xjff, 64, sWq + 64,  192, cbk0, cbk1,  kbuf + 256, 64, lane);
        mm64_store<4, false>(xi,   64, sWq + 128, 192, cbv0, cbv1,  vbuf,       64, lane);
        mm64_store<4, false>(xjff, 64, sWq + 128, 192, cbv0, cbv1,  vbuf + 256, 64, lane);
        __syncwarp();

        // attention: 16 active lanes = 4 heads x 4 query tokens; o written in-place over q
        if (lane < 16) {
            const int h = lane >> 2, s = lane & 3;
            float q[16];
            const float* qp = qox + s * 64 + h * 16;
#pragma unroll
            for (int d = 0; d < 16; d++) q[d] = qp[d];
            float scr[8];
#pragma unroll
            for (int t = 0; t < 8; t++) {
                const float* kp = kbuf + t * 64 + h * 16;
                float a = 0.f;
#pragma unroll
                for (int d = 0; d < 16; d++) a = fmaf(q[d], kp[d], a);
                scr[t] = a * 0.25f;  // 1/sqrt(16)
            }
            float m = scr[0];
#pragma unroll
            for (int t = 1; t < 8; t++) m = fmaxf(m, scr[t]);
            float ssum = 0.f;
#pragma unroll
            for (int t = 0; t < 8; t++) { scr[t] = __expf(scr[t] - m); ssum += scr[t]; }
            float inv = 1.f / ssum;
            float o[16];
#pragma unroll
            for (int d = 0; d < 16; d++) o[d] = 0.f;
#pragma unroll
            for (int t = 0; t < 8; t++) {
                const float* vp = vbuf + t * 64 + h * 16;
                float p = scr[t] * inv;
#pragma unroll
                for (int d = 0; d < 16; d++) o[d] = fmaf(p, vp[d], o[d]);
            }
            float* op = qox + s * 64 + h * 16;   // in-place (own slice only)
#pragma unroll
            for (int d = 0; d < 16; d++) op[d] = o[d];
        }
        __syncwarp();

        // attn proj + residual(xi) + LN1; reads all of qox, then rewrites it
        {
            float a0[4], a1[4];
            mm64_core<4>(qox, 64, sWo, 64, lane, a0, a1);
            __syncwarp();
#pragma unroll
            for (int t = 0; t < 4; t++) {
                float r0 = a0[t] + cbo0 + xi[t * 64 + lane];
                float r1 = a1[t] + cbo1 + xi[t * 64 + lane + 32];
                float y0, y1;
                ln_pair(r0, r1, cg10, cg11, cbe10, cbe11, y0, y1);
                qox[t * 64 + lane]      = y0;
                qox[t * 64 + lane + 32] = y1;
            }
        }
        __syncwarp();

        // FF1 (relu): qox -> xjff
        mm64_store<4, true>(qox, 64, sW1, 64, cbf10, cbf11, xjff, 64, lane);
        __syncwarp();

        // FF2 + residual(qox) + LN2 -> atomic scatter
        {
            float a0[4], a1[4];
            mm64_core<4>(xjff, 64, sW2, 64, lane, a0, a1);
            float* accp = accbase + (size_t)dst * 256;
#pragma unroll
            for (int t = 0; t < 4; t++) {
                float r0 = a0[t] + cbf20 + qox[t * 64 + lane];
                float r1 = a1[t] + cbf21 + qox[t * 64 + lane + 32];
                float y0, y1;
                ln_pair(r0, r1, cg20, cg21, cbe20, cbe21, y0, y1);
                atomicAdd(accp + t * 64 + lane, y0);
                atomicAdd(accp + t * 64 + lane + 32, y1);
            }
            if (lane == 0) atomicAdd(cntbase + dst, 1);
        }
        __syncwarp();
    }
}

// ---------------------------------------------------------------------------
// final: mean across edge types, Wout per token, sum over tokens, softmax(32)
// one warp per node, 4 nodes per block
// ---------------------------------------------------------------------------
__global__ void __launch_bounds__(128) out_kernel(const float* __restrict__ Wout,
                                                  const float* __restrict__ bout,
                                                  float* __restrict__ out) {
    __shared__ float sW[2048];   // [c][o]
    __shared__ float sb[32];
    __shared__ float comb[4][256];
    const int tid = threadIdx.x;
    for (int i = tid; i < 2048; i += 128) { int o = i >> 6, c = i & 63; sW[c * 32 + o] = Wout[i]; }
    if (tid < 32) sb[tid] = bout[tid];
    __syncthreads();

    const int warp = tid >> 5, lane = tid & 31;
    const int n = blockIdx.x * 4 + warp;
    if (n >= NA_N) return;

    const int c0 = g_cnt[n], c1 = g_cnt[NA_N + n];
    const float i0 = (c0 > 0) ? 0.5f / (float)c0 : 0.f;
    const float i1 = (c1 > 0) ? 0.5f / (float)c1 : 0.f;
    const float* a0 = g_acc + (size_t)n * 256;
    const float* a1 = g_acc + (size_t)NA_N * 256 + (size_t)n * 256;
    float* cb = comb[warp];
#pragma unroll
    for (int j = 0; j < 8; j++) {
        int i = lane + 32 * j;
        cb[i] = a0[i] * i0 + a1[i] * i1;
    }
    __syncwarp();

    float h = 0.f;
#pragma unroll 4
    for (int i = 0; i < 256; i++) {
        int c = i & 63;
        h = fmaf(cb[i], sW[c * 32 + lane], h);
    }
    h += 4.f * sb[lane];

    float m = warp_max(h);
    float ex = __expf(h - m);
    float s = warp_sum(ex);
    out[(size_t)n * 32 + lane] = ex / s;
}

// ---------------------------------------------------------------------------
extern "C" void kernel_launch(void* const* d_in, const int* in_sizes, int n_in,
                              void* d_out, int out_size) {
    const float* xA   = (const float*)d_in[0];
    const float* xB   = (const float*)d_in[1];
    const int*   e0   = (const int*)d_in[2];
    const int*   e1   = (const int*)d_in[3];
    const float* Wb   = (const float*)d_in[4];
    const float* bb   = (const float*)d_in[5];
    const float* Wqkv = (const float*)d_in[6];
    const float* bqkv = (const float*)d_in[7];
    const float* Wo   = (const float*)d_in[8];
    const float* bo   = (const float*)d_in[9];
    const float* g1   = (const float*)d_in[10];
    const float* be1  = (const float*)d_in[11];
    const float* W1   = (const float*)d_in[12];
    const float* bf1  = (const float*)d_in[13];
    const float* W2   = (const float*)d_in[14];
    const float* bf2  = (const float*)d_in[15];
    const float* g2   = (const float*)d_in[16];
    const float* be2  = (const float*)d_in[17];
    const float* Wout = (const float*)d_in[18];
    const float* bout = (const float*)d_in[19];

    const int E0 = in_sizes[2] / 2;
    const int E1 = in_sizes[3] / 2;

    // weights 28672 floats + 16 warps * 1792 floats = 57344 floats = 229,376 B
    const int smem_bytes = (28672 + WARPS_PER_BLK * 1792) * 4;
    cudaFuncSetAttribute(edge_kernel, cudaFuncAttributeMaxDynamicSharedMemorySize, smem_bytes);

    zero_kernel<<<2048, 256>>>();
    edge_kernel<<<2 * EDGE_BLOCKS, 512, smem_bytes>>>(
        xA, xB, e0, E0, e1, E1,
        Wb, bb, Wqkv, bqkv, Wo, bo, g1, be1, W1, bf1, W2, bf2, g2, be2);
    out_kernel<<<(NA_N + 3) / 4, 128>>>(Wout, bout, (float*)d_out);
}

// round 3
// speedup vs baseline: 1.0698x; 1.0698x over previous
#include <cuda_runtime.h>
#include <math.h>

// Problem constants (fixed-shape problem)
#define NA_N   40000
#define NB_N   40000
#define EPS_LN 1e-5f

#define WARPS_PER_BLK 12
#define EDGE_BLOCKS   148          // per edge type
#define EDGE_STRIDE   (EDGE_BLOCKS * WARPS_PER_BLK)
#define THREADS_BLK   (WARPS_PER_BLK * 32)

// Scratch: per-type accumulators and counts (static device arrays; no runtime alloc)
__device__ float g_acc[2ull * NA_N * 256ull];
__device__ int   g_cnt[2 * NA_N];

// ---------------------------------------------------------------------------
// helpers
// ---------------------------------------------------------------------------
__device__ __forceinline__ float warp_sum(float v) {
#pragma unroll
    for (int o = 16; o; o >>= 1) v += __shfl_xor_sync(0xffffffffu, v, o);
    return v;
}
__device__ __forceinline__ float warp_max(float v) {
#pragma unroll
    for (int o = 16; o; o >>= 1) v = fmaxf(v, __shfl_xor_sync(0xffffffffu, v, o));
    return v;
}

// out[s][feature-pair] partials over 64-dim reduction. Weights transposed [c][f]
// in smem; lane owns features (2*lane, 2*lane+1) -> weight read is one LDS.64.
// Input rows read as broadcast float4 LDS.
template <int S>
__device__ __forceinline__ void mm64_core(const float* __restrict__ in, int in_stride,
                                          const float* __restrict__ Wt, int wstride,
                                          int lane, float2* acc) {
#pragma unroll
    for (int s = 0; s < S; s++) { acc[s].x = 0.f; acc[s].y = 0.f; }
#pragma unroll
    for (int c4 = 0; c4 < 16; c4++) {
        float4 xv[S];
#pragma unroll
        for (int s = 0; s < S; s++)
            xv[s] = *reinterpret_cast<const float4*>(in + s * in_stride + (c4 << 2));
#pragma unroll
        for (int j = 0; j < 4; j++) {
            const float2 w = *reinterpret_cast<const float2*>(
                Wt + ((c4 << 2) + j) * wstride + 2 * lane);
#pragma unroll
            for (int s = 0; s < S; s++) {
                float xx = (j == 0) ? xv[s].x : (j == 1) ? xv[s].y : (j == 2) ? xv[s].z : xv[s].w;
                acc[s].x = fmaf(xx, w.x, acc[s].x);
                acc[s].y = fmaf(xx, w.y, acc[s].y);
            }
        }
    }
}

template <int S, bool RELU>
__device__ __forceinline__ void mm64_store(const float* __restrict__ in, int in_stride,
                                           const float* __restrict__ Wt, int wstride,
                                           const float* __restrict__ bias,
                                           float* __restrict__ out, int out_stride, int lane) {
    float2 acc[S];
    mm64_core<S>(in, in_stride, Wt, wstride, lane, acc);
    const float2 bv = *reinterpret_cast<const float2*>(bias + 2 * lane);
#pragma unroll
    for (int s = 0; s < S; s++) {
        float r0 = acc[s].x + bv.x, r1 = acc[s].y + bv.y;
        if (RELU) { r0 = fmaxf(r0, 0.f); r1 = fmaxf(r1, 0.f); }
        *reinterpret_cast<float2*>(out + s * out_stride + 2 * lane) = make_float2(r0, r1);
    }
}

// LayerNorm over 64 features; lane owns pair (2*lane, 2*lane+1).
__device__ __forceinline__ void ln_pair(float r0, float r1,
                                        const float* __restrict__ g, const float* __restrict__ b,
                                        int lane, float& y0, float& y1) {
    float m = warp_sum(r0 + r1) * (1.f / 64.f);
    float d0 = r0 - m, d1 = r1 - m;
    float v = warp_sum(d0 * d0 + d1 * d1) * (1.f / 64.f);
    float inv = rsqrtf(v + EPS_LN);
    const float2 gv = *reinterpret_cast<const float2*>(g + 2 * lane);
    const float2 bv = *reinterpret_cast<const float2*>(b + 2 * lane);
    y0 = d0 * inv * gv.x + bv.x;
    y1 = d1 * inv * gv.y + bv.y;
}

// ---------------------------------------------------------------------------
// zero scratch
// ---------------------------------------------------------------------------
__global__ void zero_kernel() {
    size_t i = (size_t)blockIdx.x * blockDim.x + threadIdx.x;
    size_t stride = (size_t)gridDim.x * blockDim.x;
    float4* p = reinterpret_cast<float4*>(g_acc);
    size_t n4 = (2ull * NA_N * 256ull) / 4;
    for (size_t j = i; j < n4; j += stride) p[j] = make_float4(0.f, 0.f, 0.f, 0.f);
    for (size_t j = i; j < 2 * NA_N; j += stride) g_cnt[j] = 0;
}

// ---------------------------------------------------------------------------
// per-edge transformer. grid = 2*EDGE_BLOCKS: type = blockIdx&1.
// One warp = one edge; only tokens 0..3 materialized after attention.
// Per-warp smem (1792 floats): xi[256] | xjff[256] | qox[256] | k[512] | v[512]
// ---------------------------------------------------------------------------
__global__ void __launch_bounds__(THREADS_BLK, 1) edge_kernel(
    const float* __restrict__ xA, const float* __restrict__ xB,
    const int* __restrict__ e0, int E0,
    const int* __restrict__ e1, int E1,
    const float* __restrict__ Wb,  const float* __restrict__ bb,
    const float* __restrict__ Wqkv,const float* __restrict__ bqkv,
    const float* __restrict__ Wo,  const float* __restrict__ bo,
    const float* __restrict__ g1,  const float* __restrict__ be1,
    const float* __restrict__ W1,  const float* __restrict__ bf1,
    const float* __restrict__ W2,  const float* __restrict__ bf2,
    const float* __restrict__ g2,  const float* __restrict__ be2) {
    extern __shared__ float smem[];
    float* sWb  = smem;              // [c][f]     64*64
    float* sWq  = sWb + 4096;        // [c][g]     64*192
    float* sWo  = sWq + 12288;       // [c][f]     64*64
    float* sW1  = sWo + 4096;        // [c][f]     64*64
    float* sW2  = sW1 + 4096;        // [f][c]     64*64
    float* sbb  = sW2 + 4096;        // 64
    float* sbq  = sbb + 64;          // 192
    float* sbo  = sbq + 192;         // 64
    float* sbf1 = sbo + 64;          // 64
    float* sbf2 = sbf1 + 64;         // 64
    float* sg1  = sbf2 + 64;
    float* sbe1 = sg1 + 64;
    float* sg2  = sbe1 + 64;
    float* sbe2 = sg2 + 64;
    float* bufs = sbe2 + 64;         // per-warp buffers: 1792 floats each

    const int type = blockIdx.x & 1;
    const int bidx = blockIdx.x >> 1;
    const int tid = threadIdx.x;

    // Stage weights (transposed so the reduction dim is the smem row)
    {
        const float* p;
        p = Wb + type * 4096;
        for (int i = tid; i < 4096; i += THREADS_BLK)  { int f = i >> 6, c = i & 63; sWb[c * 64 + f] = p[i]; }
        p = Wqkv + type * 12288;
        for (int i = tid; i < 12288; i += THREADS_BLK) { int g = i >> 6, c = i & 63; sWq[c * 192 + g] = p[i]; }
        p = Wo + type * 4096;
        for (int i = tid; i < 4096; i += THREADS_BLK)  { int f = i >> 6, c = i & 63; sWo[c * 64 + f] = p[i]; }
        p = W1 + type * 4096;
        for (int i = tid; i < 4096; i += THREADS_BLK)  { int f = i >> 6, c = i & 63; sW1[c * 64 + f] = p[i]; }
        p = W2 + type * 4096;                  // (C, FF): out c = sum_f  ->  sW2[f][c]
        for (int i = tid; i < 4096; i += THREADS_BLK)  { int c = i >> 6, f = i & 63; sW2[f * 64 + c] = p[i]; }
        if (tid < 64)  sbb[tid]  = bb[type * 64 + tid];
        if (tid < 192) sbq[tid]  = bqkv[type * 192 + tid];
        if (tid < 64)  sbo[tid]  = bo[type * 64 + tid];
        if (tid < 64)  sbf1[tid] = bf1[type * 64 + tid];
        if (tid < 64)  sbf2[tid] = bf2[type * 64 + tid];
        if (tid < 64)  sg1[tid]  = g1[type * 64 + tid];
        if (tid < 64)  sbe1[tid] = be1[type * 64 + tid];
        if (tid < 64)  sg2[tid]  = g2[type * 64 + tid];
        if (tid < 64)  sbe2[tid] = be2[type * 64 + tid];
    }
    __syncthreads();

    const int warp = tid >> 5, lane = tid & 31;
    float* xi   = bufs + warp * 1792;
    float* xjff = xi + 256;
    float* qox  = xjff + 256;
    float* kbuf = qox + 256;     // xs staged here first (dead before k is written)
    float* vbuf = kbuf + 512;

    const float* xsrc = type ? xA : xB;
    const int*   ei   = type ? e1 : e0;
    const int    E    = type ? E1 : E0;
    float* accbase = g_acc + (size_t)type * NA_N * 256ull;
    int*   cntbase = g_cnt + type * NA_N;

    for (int e = bidx * WARPS_PER_BLK + warp; e < E; e += EDGE_STRIDE) {
        const int src = __ldg(ei + e);
        const int dst = __ldg(ei + E + e);

        // Stage xi, xs (coalesced LDG.128 -> smem; later reads are LDS broadcast)
        {
            const float4* gxi = reinterpret_cast<const float4*>(xA + (size_t)dst * 256);
            const float4* gxs = reinterpret_cast<const float4*>(xsrc + (size_t)src * 256);
            float4 a = __ldg(gxi + lane);
            float4 b = __ldg(gxi + lane + 32);
            float4 c = __ldg(gxs + lane);
            float4 d = __ldg(gxs + lane + 32);
            reinterpret_cast<float4*>(xi)[lane]        = a;
            reinterpret_cast<float4*>(xi)[lane + 32]   = b;
            reinterpret_cast<float4*>(kbuf)[lane]      = c;
            reinterpret_cast<float4*>(kbuf)[lane + 32] = d;
        }
        __syncwarp();

        // b_proj: xs(kbuf) -> xjff
        mm64_store<4, false>(kbuf, 64, sWb, 64, sbb, xjff, 64, lane);
        __syncwarp();

        // q (rows 0..3 only), k, v
        mm64_store<4, false>(xi,   64, sWq + 0,   192, sbq + 0,   qox,        64, lane);
        mm64_store<4, false>(xi,   64, sWq + 64,  192, sbq + 64,  kbuf,       64, lane);
        mm64_store<4, false>(xjff, 64, sWq + 64,  192, sbq + 64,  kbuf + 256, 64, lane);
        mm64_store<4, false>(xi,   64, sWq + 128, 192, sbq + 128, vbuf,       64, lane);
        mm64_store<4, false>(xjff, 64, sWq + 128, 192, sbq + 128, vbuf + 256, 64, lane);
        __syncwarp();

        // attention: 16 active lanes = 4 heads x 4 query tokens; o in-place over q
        if (lane < 16) {
            const int h = lane >> 2, s = lane & 3;
            float q[16];
            const float* qp = qox + s * 64 + h * 16;
#pragma unroll
            for (int d = 0; d < 16; d++) q[d] = qp[d];
            float scr[8];
#pragma unroll
            for (int t = 0; t < 8; t++) {
                const float* kp = kbuf + t * 64 + h * 16;
                float a = 0.f;
#pragma unroll
                for (int d = 0; d < 16; d++) a = fmaf(q[d], kp[d], a);
                scr[t] = a * 0.25f;  // 1/sqrt(16)
            }
            float m = scr[0];
#pragma unroll
            for (int t = 1; t < 8; t++) m = fmaxf(m, scr[t]);
            float ssum = 0.f;
#pragma unroll
            for (int t = 0; t < 8; t++) { scr[t] = __expf(scr[t] - m); ssum += scr[t]; }
            float inv = 1.f / ssum;
            float o[16];
#pragma unroll
            for (int d = 0; d < 16; d++) o[d] = 0.f;
#pragma unroll
            for (int t = 0; t < 8; t++) {
                const float* vp = vbuf + t * 64 + h * 16;
                float p = scr[t] * inv;
#pragma unroll
                for (int d = 0; d < 16; d++) o[d] = fmaf(p, vp[d], o[d]);
            }
            float* op = qox + s * 64 + h * 16;   // in-place (own slice only)
#pragma unroll
            for (int d = 0; d < 16; d++) op[d] = o[d];
        }
        __syncwarp();

        // attn proj + residual(xi) + LN1; reads all of qox, then rewrites it
        {
            float2 acc[4];
            mm64_core<4>(qox, 64, sWo, 64, lane, acc);
            __syncwarp();
            const float2 bv = *reinterpret_cast<const float2*>(sbo + 2 * lane);
#pragma unroll
            for (int t = 0; t < 4; t++) {
                const float2 xv = *reinterpret_cast<const float2*>(xi + t * 64 + 2 * lane);
                float r0 = acc[t].x + bv.x + xv.x;
                float r1 = acc[t].y + bv.y + xv.y;
                float y0, y1;
                ln_pair(r0, r1, sg1, sbe1, lane, y0, y1);
                *reinterpret_cast<float2*>(qox + t * 64 + 2 * lane) = make_float2(y0, y1);
            }
        }
        __syncwarp();

        // FF1 (relu): qox -> xjff
        mm64_store<4, true>(qox, 64, sW1, 64, sbf1, xjff, 64, lane);
        __syncwarp();

        // FF2 + residual(qox) + LN2 -> atomic scatter
        {
            float2 acc[4];
            mm64_core<4>(xjff, 64, sW2, 64, lane, acc);
            const float2 bv = *reinterpret_cast<const float2*>(sbf2 + 2 * lane);
            float* accp = accbase + (size_t)dst * 256;
#pragma unroll
            for (int t = 0; t < 4; t++) {
                const float2 xv = *reinterpret_cast<const float2*>(qox + t * 64 + 2 * lane);
                float r0 = acc[t].x + bv.x + xv.x;
                float r1 = acc[t].y + bv.y + xv.y;
                float y0, y1;
                ln_pair(r0, r1, sg2, sbe2, lane, y0, y1);
                atomicAdd(accp + t * 64 + 2 * lane,     y0);
                atomicAdd(accp + t * 64 + 2 * lane + 1, y1);
            }
            if (lane == 0) atomicAdd(cntbase + dst, 1);
        }
        __syncwarp();
    }
}

// ---------------------------------------------------------------------------
// final: mean across edge types, Wout per token, sum over tokens, softmax(32)
// one warp per node, 4 nodes per block
// ---------------------------------------------------------------------------
__global__ void __launch_bounds__(128) out_kernel(const float* __restrict__ Wout,
                                                  const float* __restrict__ bout,
                                                  float* __restrict__ out) {
    __shared__ float sW[2048];   // [c][o]
    __shared__ float sb[32];
    __shared__ float comb[4][256];
    const int tid = threadIdx.x;
    for (int i = tid; i < 2048; i += 128) { int o = i >> 6, c = i & 63; sW[c * 32 + o] = Wout[i]; }
    if (tid < 32) sb[tid] = bout[tid];
    __syncthreads();

    const int warp = tid >> 5, lane = tid & 31;
    const int n = blockIdx.x * 4 + warp;
    if (n >= NA_N) return;

    const int c0 = g_cnt[n], c1 = g_cnt[NA_N + n];
    const float i0 = (c0 > 0) ? 0.5f / (float)c0 : 0.f;
    const float i1 = (c1 > 0) ? 0.5f / (float)c1 : 0.f;
    const float* a0 = g_acc + (size_t)n * 256;
    const float* a1 = g_acc + (size_t)NA_N * 256 + (size_t)n * 256;
    float* cb = comb[warp];
#pragma unroll
    for (int j = 0; j < 8; j++) {
        int i = lane + 32 * j;
        cb[i] = a0[i] * i0 + a1[i] * i1;
    }
    __syncwarp();

    float h = 0.f;
#pragma unroll 4
    for (int i = 0; i < 256; i++) {
        int c = i & 63;
        h = fmaf(cb[i], sW[c * 32 + lane], h);
    }
    h += 4.f * sb[lane];

    float m = warp_max(h);
    float ex = __expf(h - m);
    float s = warp_sum(ex);
    out[(size_t)n * 32 + lane] = ex / s;
}

// ---------------------------------------------------------------------------
extern "C" void kernel_launch(void* const* d_in, const int* in_sizes, int n_in,
                              void* d_out, int out_size) {
    const float* xA   = (const float*)d_in[0];
    const float* xB   = (const float*)d_in[1];
    const int*   e0   = (const int*)d_in[2];
    const int*   e1   = (const int*)d_in[3];
    const float* Wb   = (const float*)d_in[4];
    const float* bb   = (const float*)d_in[5];
    const float* Wqkv = (const float*)d_in[6];
    const float* bqkv = (const float*)d_in[7];
    const float* Wo   = (const float*)d_in[8];
    const float* bo   = (const float*)d_in[9];
    const float* g1   = (const float*)d_in[10];
    const float* be1  = (const float*)d_in[11];
    const float* W1   = (const float*)d_in[12];
    const float* bf1  = (const float*)d_in[13];
    const float* W2   = (const float*)d_in[14];
    const float* bf2  = (const float*)d_in[15];
    const float* g2   = (const float*)d_in[16];
    const float* be2  = (const float*)d_in[17];
    const float* Wout = (const float*)d_in[18];
    const float* bout = (const float*)d_in[19];

    const int E0 = in_sizes[2] / 2;
    const int E1 = in_sizes[3] / 2;

    // weights 28672 + biases 704 + 12 warps * 1792 = 50880 floats = 203,520 B
    const int smem_bytes = (28672 + 704 + WARPS_PER_BLK * 1792) * 4;
    cudaFuncSetAttribute(edge_kernel, cudaFuncAttributeMaxDynamicSharedMemorySize, smem_bytes);

    zero_kernel<<<2048, 256>>>();
    edge_kernel<<<2 * EDGE_BLOCKS, THREADS_BLK, smem_bytes>>>(
        xA, xB, e0, E0, e1, E1,
        Wb, bb, Wqkv, bqkv, Wo, bo, g1, be1, W1, bf1, W2, bf2, g2, be2);
    out_kernel<<<(NA_N + 3) / 4, 128>>>(Wout, bout, (float*)d_out);
}

// round 4
// speedup vs baseline: 3.3330x; 3.1155x over previous
#include <cuda_runtime.h>
#include <math.h>

// Problem constants (fixed-shape problem)
#define NA_N   40000
#define NB_N   40000
#define EPS_LN 1e-5f

#define WARPS_PER_BLK 8
#define EDGE_BLOCKS   148          // per edge type
#define EDGE_STRIDE   (EDGE_BLOCKS * WARPS_PER_BLK)
#define THREADS_BLK   (WARPS_PER_BLK * 32)

// Scratch: per-type accumulators and counts (static device arrays; no runtime alloc)
__device__ float g_acc[2ull * NA_N * 256ull];
__device__ int   g_cnt[2 * NA_N];

// ---------------------------------------------------------------------------
// helpers
// ---------------------------------------------------------------------------
__device__ __forceinline__ float warp_sum(float v) {
#pragma unroll
    for (int o = 16; o; o >>= 1) v += __shfl_xor_sync(0xffffffffu, v, o);
    return v;
}
__device__ __forceinline__ float warp_max(float v) {
#pragma unroll
    for (int o = 16; o; o >>= 1) v = fmaxf(v, __shfl_xor_sync(0xffffffffu, v, o));
    return v;
}

// Single-matrix GEMM core: out[s][f] partials over 64-dim reduction.
// Weights [c][f] in smem, lane owns (lane, lane+32) -> two LDS.32, conflict-free.
// Input rows read as broadcast float4 LDS.
template <int S>
__device__ __forceinline__ void mm64_core(const float* __restrict__ in, int in_stride,
                                          const float* __restrict__ Wt, int wstride,
                                          int lane, float* a0, float* a1) {
#pragma unroll
    for (int s = 0; s < S; s++) { a0[s] = 0.f; a1[s] = 0.f; }
#pragma unroll
    for (int c4 = 0; c4 < 16; c4++) {
        float4 xv[S];
#pragma unroll
        for (int s = 0; s < S; s++)
            xv[s] = *reinterpret_cast<const float4*>(in + s * in_stride + (c4 << 2));
#pragma unroll
        for (int j = 0; j < 4; j++) {
            const float* wrow = Wt + ((c4 << 2) + j) * wstride;
            float w0 = wrow[lane];
            float w1 = wrow[lane + 32];
#pragma unroll
            for (int s = 0; s < S; s++) {
                float xx = (j == 0) ? xv[s].x : (j == 1) ? xv[s].y : (j == 2) ? xv[s].z : xv[s].w;
                a0[s] = fmaf(xx, w0, a0[s]);
                a1[s] = fmaf(xx, w1, a1[s]);
            }
        }
    }
}

template <int S, bool RELU>
__device__ __forceinline__ void mm64_store(const float* __restrict__ in, int in_stride,
                                           const float* __restrict__ Wt, int wstride,
                                           const float* __restrict__ bias,
                                           float* __restrict__ out, int out_stride, int lane) {
    float a0[S], a1[S];
    mm64_core<S>(in, in_stride, Wt, wstride, lane, a0, a1);
    float b0 = bias[lane], b1 = bias[lane + 32];
#pragma unroll
    for (int s = 0; s < S; s++) {
        float r0 = a0[s] + b0, r1 = a1[s] + b1;
        if (RELU) { r0 = fmaxf(r0, 0.f); r1 = fmaxf(r1, 0.f); }
        out[s * out_stride + lane]      = r0;
        out[s * out_stride + lane + 32] = r1;
    }
}

// Fused multi-matrix sweep: one pass over the 64-dim reduction, M weight streams
// at column offsets within sWq ([c][192] layout). Each input float4 feeds M
// independent FMA chains -> 3x less input traffic, 3x ILP per load.
template <int M>
__device__ __forceinline__ void mmqkv_core(const float* __restrict__ in,
                                           const float* __restrict__ Wq, const int* woff,
                                           int lane, float (*a0)[4], float (*a1)[4]) {
#pragma unroll
    for (int m = 0; m < M; m++)
#pragma unroll
        for (int s = 0; s < 4; s++) { a0[m][s] = 0.f; a1[m][s] = 0.f; }
#pragma unroll
    for (int c4 = 0; c4 < 16; c4++) {
        float4 xv[4];
#pragma unroll
        for (int s = 0; s < 4; s++)
            xv[s] = *reinterpret_cast<const float4*>(in + s * 64 + (c4 << 2));
#pragma unroll
        for (int j = 0; j < 4; j++) {
            const float* wrow = Wq + ((c4 << 2) + j) * 192;
            float w0[M], w1[M];
#pragma unroll
            for (int m = 0; m < M; m++) {
                w0[m] = wrow[woff[m] + lane];
                w1[m] = wrow[woff[m] + lane + 32];
            }
#pragma unroll
            for (int s = 0; s < 4; s++) {
                float xx = (j == 0) ? xv[s].x : (j == 1) ? xv[s].y : (j == 2) ? xv[s].z : xv[s].w;
#pragma unroll
                for (int m = 0; m < M; m++) {
                    a0[m][s] = fmaf(xx, w0[m], a0[m][s]);
                    a1[m][s] = fmaf(xx, w1[m], a1[m][s]);
                }
            }
        }
    }
}

// LayerNorm over 64 features distributed as (lane, lane+32).
__device__ __forceinline__ void ln_pair(float r0, float r1,
                                        const float* __restrict__ g, const float* __restrict__ b,
                                        int lane, float& y0, float& y1) {
    float m = warp_sum(r0 + r1) * (1.f / 64.f);
    float d0 = r0 - m, d1 = r1 - m;
    float v = warp_sum(d0 * d0 + d1 * d1) * (1.f / 64.f);
    float inv = rsqrtf(v + EPS_LN);
    y0 = d0 * inv * g[lane]      + b[lane];
    y1 = d1 * inv * g[lane + 32] + b[lane + 32];
}

// ---------------------------------------------------------------------------
// zero scratch
// ---------------------------------------------------------------------------
__global__ void zero_kernel() {
    size_t i = (size_t)blockIdx.x * blockDim.x + threadIdx.x;
    size_t stride = (size_t)gridDim.x * blockDim.x;
    float4* p = reinterpret_cast<float4*>(g_acc);
    size_t n4 = (2ull * NA_N * 256ull) / 4;
    for (size_t j = i; j < n4; j += stride) p[j] = make_float4(0.f, 0.f, 0.f, 0.f);
    for (size_t j = i; j < 2 * NA_N; j += stride) g_cnt[j] = 0;
}

// ---------------------------------------------------------------------------
// per-edge transformer. grid = 2*EDGE_BLOCKS: type = blockIdx&1.
// One warp = one edge; only tokens 0..3 materialized after attention.
// Per-warp smem (1792 floats): xi[256] | xjff[256] | qox[256] | k[512] | v[512]
// ---------------------------------------------------------------------------
__global__ void __launch_bounds__(THREADS_BLK, 1) edge_kernel(
    const float* __restrict__ xA, const float* __restrict__ xB,
    const int* __restrict__ e0, int E0,
    const int* __restrict__ e1, int E1,
    const float* __restrict__ Wb,  const float* __restrict__ bb,
    const float* __restrict__ Wqkv,const float* __restrict__ bqkv,
    const float* __restrict__ Wo,  const float* __restrict__ bo,
    const float* __restrict__ g1,  const float* __restrict__ be1,
    const float* __restrict__ W1,  const float* __restrict__ bf1,
    const float* __restrict__ W2,  const float* __restrict__ bf2,
    const float* __restrict__ g2,  const float* __restrict__ be2) {
    extern __shared__ float smem[];
    float* sWb  = smem;              // [c][f]     64*64
    float* sWq  = sWb + 4096;        // [c][g]     64*192 (q|k|v columns)
    float* sWo  = sWq + 12288;       // [c][f]     64*64
    float* sW1  = sWo + 4096;        // [c][f]     64*64
    float* sW2  = sW1 + 4096;        // [f][c]     64*64
    float* sbb  = sW2 + 4096;        // 64
    float* sbq  = sbb + 64;          // 192
    float* sbo  = sbq + 192;         // 64
    float* sbf1 = sbo + 64;          // 64
    float* sbf2 = sbf1 + 64;         // 64
    float* sg1  = sbf2 + 64;
    float* sbe1 = sg1 + 64;
    float* sg2  = sbe1 + 64;
    float* sbe2 = sg2 + 64;
    float* bufs = sbe2 + 64;         // per-warp buffers: 1792 floats each

    const int type = blockIdx.x & 1;
    const int bidx = blockIdx.x >> 1;
    const int tid = threadIdx.x;

    // Stage weights (transposed so the reduction dim is the smem row)
    {
        const float* p;
        p = Wb + type * 4096;
        for (int i = tid; i < 4096; i += THREADS_BLK)  { int f = i >> 6, c = i & 63; sWb[c * 64 + f] = p[i]; }
        p = Wqkv + type * 12288;
        for (int i = tid; i < 12288; i += THREADS_BLK) { int g = i >> 6, c = i & 63; sWq[c * 192 + g] = p[i]; }
        p = Wo + type * 4096;
        for (int i = tid; i < 4096; i += THREADS_BLK)  { int f = i >> 6, c = i & 63; sWo[c * 64 + f] = p[i]; }
        p = W1 + type * 4096;
        for (int i = tid; i < 4096; i += THREADS_BLK)  { int f = i >> 6, c = i & 63; sW1[c * 64 + f] = p[i]; }
        p = W2 + type * 4096;                  // (C, FF): out c = sum_f  ->  sW2[f][c]
        for (int i = tid; i < 4096; i += THREADS_BLK)  { int c = i >> 6, f = i & 63; sW2[f * 64 + c] = p[i]; }
        if (tid < 64)  sbb[tid]  = bb[type * 64 + tid];
        if (tid < 192) sbq[tid]  = bqkv[type * 192 + tid];
        if (tid < 64)  sbo[tid]  = bo[type * 64 + tid];
        if (tid < 64)  sbf1[tid] = bf1[type * 64 + tid];
        if (tid < 64)  sbf2[tid] = bf2[type * 64 + tid];
        if (tid < 64)  sg1[tid]  = g1[type * 64 + tid];
        if (tid < 64)  sbe1[tid] = be1[type * 64 + tid];
        if (tid < 64)  sg2[tid]  = g2[type * 64 + tid];
        if (tid < 64)  sbe2[tid] = be2[type * 64 + tid];
    }
    __syncthreads();

    const int warp = tid >> 5, lane = tid & 31;
    float* xi   = bufs + warp * 1792;
    float* xjff = xi + 256;
    float* qox  = xjff + 256;
    float* kbuf = qox + 256;     // xs staged here first (dead before k is written)
    float* vbuf = kbuf + 512;

    const float* xsrc = type ? xA : xB;
    const int*   ei   = type ? e1 : e0;
    const int    E    = type ? E1 : E0;
    float* accbase = g_acc + (size_t)type * NA_N * 256ull;
    int*   cntbase = g_cnt + type * NA_N;

    const int woff3[3] = {0, 64, 128};   // q, k, v column offsets in sWq
    const int woff2[2] = {64, 128};      // k, v

    for (int e = bidx * WARPS_PER_BLK + warp; e < E; e += EDGE_STRIDE) {
        const int src = __ldg(ei + e);
        const int dst = __ldg(ei + E + e);

        // Stage xi, xs (coalesced LDG.128 -> smem; later reads are LDS broadcast)
        {
            const float4* gxi = reinterpret_cast<const float4*>(xA + (size_t)dst * 256);
            const float4* gxs = reinterpret_cast<const float4*>(xsrc + (size_t)src * 256);
            float4 a = __ldg(gxi + lane);
            float4 b = __ldg(gxi + lane + 32);
            float4 c = __ldg(gxs + lane);
            float4 d = __ldg(gxs + lane + 32);
            reinterpret_cast<float4*>(xi)[lane]        = a;
            reinterpret_cast<float4*>(xi)[lane + 32]   = b;
            reinterpret_cast<float4*>(kbuf)[lane]      = c;
            reinterpret_cast<float4*>(kbuf)[lane + 32] = d;
        }
        __syncwarp();

        // b_proj: xs(kbuf) -> xjff
        mm64_store<4, false>(kbuf, 64, sWb, 64, sbb, xjff, 64, lane);
        __syncwarp();

        // fused q,k,v from xi (overwrites kbuf[0:256]: xs is dead)
        {
            float a0[3][4], a1[3][4];
            mmqkv_core<3>(xi, sWq, woff3, lane, a0, a1);
            float bq0 = sbq[lane],       bq1 = sbq[lane + 32];
            float bk0 = sbq[64 + lane],  bk1 = sbq[64 + lane + 32];
            float bv0 = sbq[128 + lane], bv1 = sbq[128 + lane + 32];
#pragma unroll
            for (int s = 0; s < 4; s++) {
                qox[s * 64 + lane]       = a0[0][s] + bq0;
                qox[s * 64 + lane + 32]  = a1[0][s] + bq1;
                kbuf[s * 64 + lane]      = a0[1][s] + bk0;
                kbuf[s * 64 + lane + 32] = a1[1][s] + bk1;
                vbuf[s * 64 + lane]      = a0[2][s] + bv0;
                vbuf[s * 64 + lane + 32] = a1[2][s] + bv1;
            }
        }
        // fused k,v from xjff
        {
            float a0[2][4], a1[2][4];
            mmqkv_core<2>(xjff, sWq, woff2, lane, a0, a1);
            float bk0 = sbq[64 + lane],  bk1 = sbq[64 + lane + 32];
            float bv0 = sbq[128 + lane], bv1 = sbq[128 + lane + 32];
#pragma unroll
            for (int s = 0; s < 4; s++) {
                kbuf[256 + s * 64 + lane]      = a0[0][s] + bk0;
                kbuf[256 + s * 64 + lane + 32] = a1[0][s] + bk1;
                vbuf[256 + s * 64 + lane]      = a0[1][s] + bv0;
                vbuf[256 + s * 64 + lane + 32] = a1[1][s] + bv1;
            }
        }
        __syncwarp();

        // attention: 16 active lanes = 4 heads x 4 query tokens; o in-place over q
        if (lane < 16) {
            const int h = lane >> 2, s = lane & 3;
            float q[16];
            const float* qp = qox + s * 64 + h * 16;
#pragma unroll
            for (int d = 0; d < 16; d++) q[d] = qp[d];
            float scr[8];
#pragma unroll
            for (int t = 0; t < 8; t++) {
                const float* kp = kbuf + t * 64 + h * 16;
                float a = 0.f;
#pragma unroll
                for (int d = 0; d < 16; d++) a = fmaf(q[d], kp[d], a);
                scr[t] = a * 0.25f;  // 1/sqrt(16)
            }
            float m = scr[0];
#pragma unroll
            for (int t = 1; t < 8; t++) m = fmaxf(m, scr[t]);
            float ssum = 0.f;
#pragma unroll
            for (int t = 0; t < 8; t++) { scr[t] = __expf(scr[t] - m); ssum += scr[t]; }
            float inv = 1.f / ssum;
            float o[16];
#pragma unroll
            for (int d = 0; d < 16; d++) o[d] = 0.f;
#pragma unroll
            for (int t = 0; t < 8; t++) {
                const float* vp = vbuf + t * 64 + h * 16;
                float p = scr[t] * inv;
#pragma unroll
                for (int d = 0; d < 16; d++) o[d] = fmaf(p, vp[d], o[d]);
            }
            float* op = qox + s * 64 + h * 16;   // in-place (own slice only)
#pragma unroll
            for (int d = 0; d < 16; d++) op[d] = o[d];
        }
        __syncwarp();

        // attn proj + residual(xi) + LN1; reads all of qox, then rewrites it
        {
            float a0[4], a1[4];
            mm64_core<4>(qox, 64, sWo, 64, lane, a0, a1);
            __syncwarp();
            float b0 = sbo[lane], b1 = sbo[lane + 32];
#pragma unroll
            for (int t = 0; t < 4; t++) {
                float r0 = a0[t] + b0 + xi[t * 64 + lane];
                float r1 = a1[t] + b1 + xi[t * 64 + lane + 32];
                float y0, y1;
                ln_pair(r0, r1, sg1, sbe1, lane, y0, y1);
                qox[t * 64 + lane]      = y0;
                qox[t * 64 + lane + 32] = y1;
            }
        }
        __syncwarp();

        // FF1 (relu): qox -> xjff
        mm64_store<4, true>(qox, 64, sW1, 64, sbf1, xjff, 64, lane);
        __syncwarp();

        // FF2 + residual(qox) + LN2 -> atomic scatter
        {
            float a0[4], a1[4];
            mm64_core<4>(xjff, 64, sW2, 64, lane, a0, a1);
            float b0 = sbf2[lane], b1 = sbf2[lane + 32];
            float* accp = accbase + (size_t)dst * 256;
#pragma unroll
            for (int t = 0; t < 4; t++) {
                float r0 = a0[t] + b0 + qox[t * 64 + lane];
                float r1 = a1[t] + b1 + qox[t * 64 + lane + 32];
                float y0, y1;
                ln_pair(r0, r1, sg2, sbe2, lane, y0, y1);
                atomicAdd(accp + t * 64 + lane, y0);
                atomicAdd(accp + t * 64 + lane + 32, y1);
            }
            if (lane == 0) atomicAdd(cntbase + dst, 1);
        }
        __syncwarp();
    }
}

// ---------------------------------------------------------------------------
// final: mean across edge types, Wout per token, sum over tokens, softmax(32)
// one warp per node, 4 nodes per block
// ---------------------------------------------------------------------------
__global__ void __launch_bounds__(128) out_kernel(const float* __restrict__ Wout,
                                                  const float* __restrict__ bout,
                                                  float* __restrict__ out) {
    __shared__ float sW[2048];   // [c][o]
    __shared__ float sb[32];
    __shared__ float comb[4][256];
    const int tid = threadIdx.x;
    for (int i = tid; i < 2048; i += 128) { int o = i >> 6, c = i & 63; sW[c * 32 + o] = Wout[i]; }
    if (tid < 32) sb[tid] = bout[tid];
    __syncthreads();

    const int warp = tid >> 5, lane = tid & 31;
    const int n = blockIdx.x * 4 + warp;
    if (n >= NA_N) return;

    const int c0 = g_cnt[n], c1 = g_cnt[NA_N + n];
    const float i0 = (c0 > 0) ? 0.5f / (float)c0 : 0.f;
    const float i1 = (c1 > 0) ? 0.5f / (float)c1 : 0.f;
    const float* a0 = g_acc + (size_t)n * 256;
    const float* a1 = g_acc + (size_t)NA_N * 256 + (size_t)n * 256;
    float* cb = comb[warp];
#pragma unroll
    for (int j = 0; j < 8; j++) {
        int i = lane + 32 * j;
        cb[i] = a0[i] * i0 + a1[i] * i1;
    }
    __syncwarp();

    float h = 0.f;
#pragma unroll 4
    for (int i = 0; i < 256; i++) {
        int c = i & 63;
        h = fmaf(cb[i], sW[c * 32 + lane], h);
    }
    h += 4.f * sb[lane];

    float m = warp_max(h);
    float ex = __expf(h - m);
    float s = warp_sum(ex);
    out[(size_t)n * 32 + lane] = ex / s;
}

// ---------------------------------------------------------------------------
extern "C" void kernel_launch(void* const* d_in, const int* in_sizes, int n_in,
                              void* d_out, int out_size) {
    const float* xA   = (const float*)d_in[0];
    const float* xB   = (const float*)d_in[1];
    const int*   e0   = (const int*)d_in[2];
    const int*   e1   = (const int*)d_in[3];
    const float* Wb   = (const float*)d_in[4];
    const float* bb   = (const float*)d_in[5];
    const float* Wqkv = (const float*)d_in[6];
    const float* bqkv = (const float*)d_in[7];
    const float* Wo   = (const float*)d_in[8];
    const float* bo   = (const float*)d_in[9];
    const float* g1   = (const float*)d_in[10];
    const float* be1  = (const float*)d_in[11];
    const float* W1   = (const float*)d_in[12];
    const float* bf1  = (const float*)d_in[13];
    const float* W2   = (const float*)d_in[14];
    const float* bf2  = (const float*)d_in[15];
    const float* g2   = (const float*)d_in[16];
    const float* be2  = (const float*)d_in[17];
    const float* Wout = (const float*)d_in[18];
    const float* bout = (const float*)d_in[19];

    const int E0 = in_sizes[2] / 2;
    const int E1 = in_sizes[3] / 2;

    // weights 28672 + biases 704 + 8 warps * 1792 = 43712 floats = 174,848 B
    const int smem_bytes = (28672 + 704 + WARPS_PER_BLK * 1792) * 4;
    cudaFuncSetAttribute(edge_kernel, cudaFuncAttributeMaxDynamicSharedMemorySize, smem_bytes);

    zero_kernel<<<2048, 256>>>();
    edge_kernel<<<2 * EDGE_BLOCKS, THREADS_BLK, smem_bytes>>>(
        xA, xB, e0, E0, e1, E1,
        Wb, bb, Wqkv, bqkv, Wo, bo, g1, be1, W1, bf1, W2, bf2, g2, be2);
    out_kernel<<<(NA_N + 3) / 4, 128>>>(Wout, bout, (float*)d_out);
}